// round 2
// baseline (speedup 1.0000x reference)
#include <cuda_runtime.h>
#include <cstdint>

// ============================================================================
// Binary conv1d (sign x sign) + maxpool(7,2) + per-channel threshold
// via classic IMMA mma.sync.m16n8k32.s8 (plain sm_103-compatible PTX).
//
// GEMM view: D[128 Cout, 64 n] = A[128, 448] * B[64, 448]^T per tile,
// K ordered kappa = j*64 + ci so B fragments are direct LDS.32 reads from a
// compact (non-im2col'd) sign tile X[pos][ci].
// ============================================================================

#define BATCH 64
#define CIN 64
#define LEN 16384
#define COUT 128
#define LOUT 8189              // (16384 + 6 - 7)/2 + 1 with pool(7,2) on 16384 conv outs
#define TILE_OUT 29            // pool outputs per tile
#define TILES_PER_B 283        // ceil(8189/29)
#define TOTAL_TILES (BATCH * TILES_PER_B)   // 18112
#define NTHREADS 256
#define GRID 148

#define KSTEPS 14              // K = 448 = 14 * 32

#define X_PITCH 80             // 64 bytes + 16 pad (conflict-free frag loads)
#define CV_PITCH 129           // ints per row (64 + pad)

__device__ unsigned int g_tile_ctr;
__global__ void reset_ctr_kernel() { g_tile_ctr = 0u; }

#define MMA_S8(d, a, b0_, b1_)                                                 \
    asm volatile(                                                              \
        "mma.sync.aligned.m16n8k32.row.col.s32.s8.s8.s32 "                     \
        "{%0,%1,%2,%3},{%4,%5,%6,%7},{%8,%9},{%0,%1,%2,%3};"                   \
        : "+r"((d)[0]), "+r"((d)[1]), "+r"((d)[2]), "+r"((d)[3])               \
        : "r"((a)[0]), "r"((a)[1]), "r"((a)[2]), "r"((a)[3]),                  \
          "r"(b0_), "r"(b1_))

__global__ void __launch_bounds__(NTHREADS, 1)
binconv_kernel(const float* __restrict__ I, const float* __restrict__ W,
               const float* __restrict__ TP, const float* __restrict__ TMi,
               const float* __restrict__ PS, const float* __restrict__ MS,
               float* __restrict__ out)
{
    __shared__ int CV[64 * CV_PITCH];              // conv results [n][co]
    __shared__ unsigned char X[70 * X_PITCH];      // sign tile [pos][ci]
    __shared__ unsigned sg;

    const int tid  = threadIdx.x;
    const int lane = tid & 31;
    const int wid  = tid >> 5;
    const int wm   = wid >> 1;        // 0..3  (M groups of 32 rows)
    const int wn   = wid & 1;         // 0..1  (N groups of 32 cols)
    const int gr   = lane >> 2;       // group id 0..7
    const int tg   = lane & 3;        // thread-in-group 0..3

    // per-thread pool role: co channel + which half of the 29 outputs
    const int co   = tid & 127;
    const int half = tid >> 7;        // 0: jo 0..14, 1: jo 15..28
    const float rtp = TP[co], rtm = TMi[co], rps = PS[co], rms = MS[co];

    // ---- load stationary A fragments (weight signs), 112 regs/thread ----
    // A row-major 16x32 frag: a_j -> row = base + gr + (j&1)*8,
    //                         kappa = 32*s + (j>>1)*16 + tg*4 + i
    // kappa = j_k*64 + ci  ->  W[row*448 + ci*7 + j_k]
    uint32_t A[2][KSTEPS][4];
    #pragma unroll
    for (int mt = 0; mt < 2; mt++) {
        #pragma unroll
        for (int s = 0; s < KSTEPS; s++) {
            #pragma unroll
            for (int j = 0; j < 4; j++) {
                const int row = wm * 32 + mt * 16 + gr + (j & 1) * 8;
                const int kap = 32 * s + (j >> 1) * 16 + tg * 4;
                uint32_t r = 0;
                #pragma unroll
                for (int i = 0; i < 4; i++) {
                    const int kk = kap + i;
                    const float w = W[row * 448 + (kk & 63) * 7 + (kk >> 6)];
                    r |= ((w < 0.f) ? 0xFFu : 0x01u) << (8 * i);
                }
                A[mt][s][j] = r;
            }
        }
    }

    // ---- persistent tile loop ----
    while (true) {
        if (tid == 0) sg = atomicAdd(&g_tile_ctr, 1u);
        __syncthreads();               // also separates prev pool reads from CV writes
        const unsigned gt = sg;
        if (gt >= TOTAL_TILES) break;

        const int b  = (int)(gt / TILES_PER_B);
        const int jt = (int)gt - b * TILES_PER_B;
        const int t0 = jt * TILE_OUT;
        const int P0 = t0 * 2;
        const int nt = min(TILE_OUT, LOUT - t0);

        // ---- build compact sign tile X[p][ci], p in [0,70) ----
        // X[p][ci] = sign(x_pad[P0 + p]) for channel ci; pad value -1
        {
            const float* Ib = I + (size_t)b * (size_t)CIN * LEN;
            #pragma unroll
            for (int it = 0; it < 5; it++) {
                const int idx = tid + it * NTHREADS;     // 1120 items total
                if (idx < 16 * 70) {
                    const int ci4 = idx / 70;
                    const int p   = idx - ci4 * 70;
                    const int gl  = P0 - 3 + p;
                    const bool inb = (gl >= 0) && (gl < LEN);
                    const float* ip = Ib + (size_t)(ci4 * 4) * LEN + gl;
                    const float v0 = inb ? ip[0]       : -1.f;
                    const float v1 = inb ? ip[LEN]     : -1.f;
                    const float v2 = inb ? ip[2 * LEN] : -1.f;
                    const float v3 = inb ? ip[3 * LEN] : -1.f;
                    const uint32_t pk = ((v0 < 0.f) ? 0xFFu : 1u)
                                      | (((v1 < 0.f) ? 0xFFu : 1u) << 8)
                                      | (((v2 < 0.f) ? 0xFFu : 1u) << 16)
                                      | (((v3 < 0.f) ? 0xFFu : 1u) << 24);
                    *(uint32_t*)&X[p * X_PITCH + ci4 * 4] = pk;
                }
            }
        }
        __syncthreads();

        // ---- MMA mainloop: 112 IMMA + 112 LDS.32 per thread ----
        int acc[2][4][4];
        #pragma unroll
        for (int mt = 0; mt < 2; mt++)
            #pragma unroll
            for (int nt8 = 0; nt8 < 4; nt8++)
                #pragma unroll
                for (int r = 0; r < 4; r++) acc[mt][nt8][r] = 0;

        #pragma unroll
        for (int s = 0; s < KSTEPS; s++) {
            #pragma unroll
            for (int nt8 = 0; nt8 < 4; nt8++) {
                const int n    = wn * 32 + nt8 * 8 + gr;
                const int prel = n + (s >> 1);
                const uint32_t* bp =
                    (const uint32_t*)&X[prel * X_PITCH + (s & 1) * 32 + tg * 4];
                const uint32_t b0 = bp[0];
                const uint32_t b1 = bp[4];          // +16 bytes
                MMA_S8(acc[0][nt8], A[0][s], b0, b1);
                MMA_S8(acc[1][nt8], A[1][s], b0, b1);
            }
        }

        // ---- stage conv results to smem CV[n][co] ----
        #pragma unroll
        for (int mt = 0; mt < 2; mt++) {
            #pragma unroll
            for (int nt8 = 0; nt8 < 4; nt8++) {
                const int n0 = wn * 32 + nt8 * 8 + tg * 2;
                const int r0 = wm * 32 + mt * 16 + gr;
                CV[n0 * CV_PITCH + r0]           = acc[mt][nt8][0];
                CV[(n0 + 1) * CV_PITCH + r0]     = acc[mt][nt8][1];
                CV[n0 * CV_PITCH + r0 + 8]       = acc[mt][nt8][2];
                CV[(n0 + 1) * CV_PITCH + r0 + 8] = acc[mt][nt8][3];
            }
        }
        __syncthreads();

        // ---- pool(7,2) + threshold + store ----
        // out[jo] = max(q[jo], q[jo+1], q[jo+2], cv[2jo+6]),
        // q[x] = max(cv[2x], cv[2x+1]); rolling q chain, 3 LDS per output.
        {
            const int jo0 = half * 15;
            if (jo0 < nt) {
                float* ob = out + ((size_t)b * COUT + co) * LOUT + t0;
                int qa = max(CV[(2 * jo0) * CV_PITCH + co],
                             CV[(2 * jo0 + 1) * CV_PITCH + co]);
                int qb = max(CV[(2 * jo0 + 2) * CV_PITCH + co],
                             CV[(2 * jo0 + 3) * CV_PITCH + co]);
                #pragma unroll
                for (int k = 0; k < 15; k++) {
                    const int jo = jo0 + k;
                    if (jo < nt && jo < 29) {
                        const int l0 = CV[(2 * jo + 4) * CV_PITCH + co];
                        const int l1 = CV[(2 * jo + 5) * CV_PITCH + co];
                        const int l2 = CV[(2 * jo + 6) * CV_PITCH + co];
                        const int qc = max(l0, l1);
                        const int mi = max(max(qa, qb), max(qc, l2));
                        const float mx = (float)mi;
                        const float pos = (mx > rtp) ? rps : -rps;
                        const float neg = (mx > rtm) ? rms : -rms;
                        ob[jo] = (mx >= 0.f) ? pos : neg;
                        qa = qb; qb = qc;
                    }
                }
            }
        }
        // next-iteration top __syncthreads() fences CV reads vs rewrites
    }
}

extern "C" void kernel_launch(void* const* d_in, const int* in_sizes, int n_in,
                              void* d_out, int out_size) {
    const float* I  = (const float*)d_in[0];
    const float* W  = (const float*)d_in[1];
    const float* tp = (const float*)d_in[2];
    const float* tm = (const float*)d_in[3];
    const float* ps = (const float*)d_in[4];
    const float* ms = (const float*)d_in[5];
    float* out = (float*)d_out;

    reset_ctr_kernel<<<1, 1>>>();
    binconv_kernel<<<GRID, NTHREADS>>>(I, W, tp, tm, ps, ms, out);
}

// round 3
// speedup vs baseline: 1.3720x; 1.3720x over previous
#include <cuda_runtime.h>
#include <cstdint>

// ============================================================================
// Binary conv1d (sign x sign) + maxpool(7,2) + per-channel threshold
// via IMMA mma.sync.m16n8k32.s8, software-pipelined across tiles:
// next tile's global loads are in flight (registers) during the MMA phase.
// ============================================================================

#define BATCH 64
#define CIN 64
#define LEN 16384
#define COUT 128
#define LOUT 8189
#define TILE_OUT 29
#define TILES_PER_B 283
#define TOTAL_TILES (BATCH * TILES_PER_B)   // 18112
#define NTHREADS 256
#define GRID 148

#define KSTEPS 14              // K = 448 = 14 * 32
#define X_PITCH 80             // 64 B + 16 pad: conflict-free LDS.32 frag loads
#define CV_PITCH 129

#define MMA_S8(d, a, b0_, b1_)                                                 \
    asm volatile(                                                              \
        "mma.sync.aligned.m16n8k32.row.col.s32.s8.s8.s32 "                     \
        "{%0,%1,%2,%3},{%4,%5,%6,%7},{%8,%9},{%0,%1,%2,%3};"                   \
        : "+r"((d)[0]), "+r"((d)[1]), "+r"((d)[2]), "+r"((d)[3])               \
        : "r"((a)[0]), "r"((a)[1]), "r"((a)[2]), "r"((a)[3]),                  \
          "r"(b0_), "r"(b1_))

__global__ void __launch_bounds__(NTHREADS, 1)
binconv_kernel(const float* __restrict__ I, const float* __restrict__ W,
               const float* __restrict__ TP, const float* __restrict__ TMi,
               const float* __restrict__ PS, const float* __restrict__ MS,
               float* __restrict__ out)
{
    __shared__ int CV[64 * CV_PITCH];
    __shared__ unsigned char X[70 * X_PITCH];

    const int tid  = threadIdx.x;
    const int lane = tid & 31;
    const int wid  = tid >> 5;
    const int wm   = wid >> 1;
    const int wn   = wid & 1;
    const int gr   = lane >> 2;
    const int tg   = lane & 3;

    const int co   = tid & 127;
    const int half = tid >> 7;
    const float rtp = TP[co], rtm = TMi[co], rps = PS[co], rms = MS[co];

    // ---- stationary A fragments (weight signs): 112 regs/thread ----
    uint32_t A[2][KSTEPS][4];
    #pragma unroll
    for (int mt = 0; mt < 2; mt++) {
        #pragma unroll
        for (int s = 0; s < KSTEPS; s++) {
            #pragma unroll
            for (int j = 0; j < 4; j++) {
                const int row = wm * 32 + mt * 16 + gr + (j & 1) * 8;
                const int kap = 32 * s + (j >> 1) * 16 + tg * 4;
                uint32_t r = 0;
                #pragma unroll
                for (int i = 0; i < 4; i++) {
                    const int kk = kap + i;
                    const float w = W[row * 448 + (kk & 63) * 7 + (kk >> 6)];
                    r |= ((w < 0.f) ? 0xFFu : 0x01u) << (8 * i);
                }
                A[mt][s][j] = r;
            }
        }
    }

    // ---- prefetch helper state: 5 items/thread, 4 floats each ----
    float pf[5][4];

    // issue global loads for tile g into pf (no waiting happens here;
    // the scoreboard wait lands at the convert step next iteration)
    auto prefetch = [&](unsigned g) {
        if (g >= TOTAL_TILES) return;
        const int b  = (int)(g / TILES_PER_B);
        const int P0 = ((int)g - b * TILES_PER_B) * TILE_OUT * 2;
        const float* Ib = I + (size_t)b * (size_t)CIN * LEN;
        #pragma unroll
        for (int it = 0; it < 5; it++) {
            const int idx = tid + it * NTHREADS;
            if (idx < 16 * 70) {
                const int ci4 = idx / 70;
                const int p   = idx - ci4 * 70;
                const int gl  = P0 - 3 + p;
                const bool inb = (gl >= 0) && (gl < LEN);
                const float* ip = Ib + (size_t)(ci4 * 4) * LEN + gl;
                pf[it][0] = inb ? ip[0]       : -1.f;
                pf[it][1] = inb ? ip[LEN]     : -1.f;
                pf[it][2] = inb ? ip[2 * LEN] : -1.f;
                pf[it][3] = inb ? ip[3 * LEN] : -1.f;
            }
        }
    };

    unsigned g = (unsigned)blockIdx.x;
    prefetch(g);

    while (g < TOTAL_TILES) {
        const unsigned gn = g + GRID;
        const int b  = (int)(g / TILES_PER_B);
        const int jt = (int)g - b * TILES_PER_B;
        const int t0 = jt * TILE_OUT;
        const int nt = min(TILE_OUT, LOUT - t0);

        // ---- convert prefetched floats -> sign tile X[p][ci] ----
        #pragma unroll
        for (int it = 0; it < 5; it++) {
            const int idx = tid + it * NTHREADS;
            if (idx < 16 * 70) {
                const int ci4 = idx / 70;
                const int p   = idx - ci4 * 70;
                const uint32_t pk = ((pf[it][0] < 0.f) ? 0xFFu : 1u)
                                  | (((pf[it][1] < 0.f) ? 0xFFu : 1u) << 8)
                                  | (((pf[it][2] < 0.f) ? 0xFFu : 1u) << 16)
                                  | (((pf[it][3] < 0.f) ? 0xFFu : 1u) << 24);
                *(uint32_t*)&X[p * X_PITCH + ci4 * 4] = pk;
            }
        }
        __syncthreads();            // X ready; prev tile's CV pool reads done

        // ---- kick off next tile's global loads (hidden under MMA) ----
        prefetch(gn);

        // ---- MMA mainloop ----
        int acc[2][4][4];
        #pragma unroll
        for (int mt = 0; mt < 2; mt++)
            #pragma unroll
            for (int n8 = 0; n8 < 4; n8++)
                #pragma unroll
                for (int r = 0; r < 4; r++) acc[mt][n8][r] = 0;

        #pragma unroll
        for (int s = 0; s < KSTEPS; s++) {
            #pragma unroll
            for (int n8 = 0; n8 < 4; n8++) {
                const int n    = wn * 32 + n8 * 8 + gr;
                const int prel = n + (s >> 1);
                const uint32_t* bp =
                    (const uint32_t*)&X[prel * X_PITCH + (s & 1) * 32 + tg * 4];
                const uint32_t b0 = bp[0];
                const uint32_t b1 = bp[4];
                MMA_S8(acc[0][n8], A[0][s], b0, b1);
                MMA_S8(acc[1][n8], A[1][s], b0, b1);
            }
        }

        // ---- stage conv results to CV[n][co] ----
        #pragma unroll
        for (int mt = 0; mt < 2; mt++) {
            #pragma unroll
            for (int n8 = 0; n8 < 4; n8++) {
                const int n0 = wn * 32 + n8 * 8 + tg * 2;
                const int r0 = wm * 32 + mt * 16 + gr;
                CV[n0 * CV_PITCH + r0]           = acc[mt][n8][0];
                CV[(n0 + 1) * CV_PITCH + r0]     = acc[mt][n8][1];
                CV[n0 * CV_PITCH + r0 + 8]       = acc[mt][n8][2];
                CV[(n0 + 1) * CV_PITCH + r0 + 8] = acc[mt][n8][3];
            }
        }
        __syncthreads();            // CV ready; all MMA reads of X done

        // ---- pool(7,2) + threshold + store ----
        {
            const int jo0 = half * 15;
            if (jo0 < nt) {
                float* ob = out + ((size_t)b * COUT + co) * LOUT + t0;
                int qa = max(CV[(2 * jo0) * CV_PITCH + co],
                             CV[(2 * jo0 + 1) * CV_PITCH + co]);
                int qb = max(CV[(2 * jo0 + 2) * CV_PITCH + co],
                             CV[(2 * jo0 + 3) * CV_PITCH + co]);
                #pragma unroll
                for (int k = 0; k < 15; k++) {
                    const int jo = jo0 + k;
                    if (jo < nt && jo < 29) {
                        const int l0 = CV[(2 * jo + 4) * CV_PITCH + co];
                        const int l1 = CV[(2 * jo + 5) * CV_PITCH + co];
                        const int l2 = CV[(2 * jo + 6) * CV_PITCH + co];
                        const int qc = max(l0, l1);
                        const int mi = max(max(qa, qb), max(qc, l2));
                        const float mx = (float)mi;
                        const float pos = (mx > rtp) ? rps : -rps;
                        const float neg = (mx > rtm) ? rms : -rms;
                        ob[jo] = (mx >= 0.f) ? pos : neg;
                        qa = qb; qb = qc;
                    }
                }
            }
        }

        g = gn;
    }
}

extern "C" void kernel_launch(void* const* d_in, const int* in_sizes, int n_in,
                              void* d_out, int out_size) {
    const float* I  = (const float*)d_in[0];
    const float* W  = (const float*)d_in[1];
    const float* tp = (const float*)d_in[2];
    const float* tm = (const float*)d_in[3];
    const float* ps = (const float*)d_in[4];
    const float* ms = (const float*)d_in[5];
    float* out = (float*)d_out;

    binconv_kernel<<<GRID, NTHREADS>>>(I, W, tp, tm, ps, ms, out);
}

// round 4
// speedup vs baseline: 1.3936x; 1.0157x over previous
#include <cuda_runtime.h>
#include <cstdint>

// ============================================================================
// Binary conv1d (sign x sign) + maxpool(7,2) + per-channel threshold.
// IMMA mma.sync.m16n8k32.s8, cross-tile software pipelining, and now
// 2 CTAs/SM (regs capped to 128 via 8Mx1N warp mapping) so one CTA's MMA
// phase overlaps the other CTA's convert/epilogue phases.
// ============================================================================

#define BATCH 64
#define CIN 64
#define LEN 16384
#define COUT 128
#define LOUT 8189
#define TILE_OUT 29
#define TILES_PER_B 283
#define TOTAL_TILES (BATCH * TILES_PER_B)   // 18112
#define NTHREADS 256
#define GRID 296                             // 2 CTAs per SM

#define KSTEPS 14              // K = 448 = 14 * 32
#define X_PITCH 80             // 64 B + 16 pad: conflict-free LDS.32 frag loads
#define CV_PITCH 129

#define MMA_S8(d, a, b0_, b1_)                                                 \
    asm volatile(                                                              \
        "mma.sync.aligned.m16n8k32.row.col.s32.s8.s8.s32 "                     \
        "{%0,%1,%2,%3},{%4,%5,%6,%7},{%8,%9},{%0,%1,%2,%3};"                   \
        : "+r"((d)[0]), "+r"((d)[1]), "+r"((d)[2]), "+r"((d)[3])               \
        : "r"((a)[0]), "r"((a)[1]), "r"((a)[2]), "r"((a)[3]),                  \
          "r"(b0_), "r"(b1_))

__global__ void __launch_bounds__(NTHREADS, 2)
binconv_kernel(const float* __restrict__ I, const float* __restrict__ W,
               const float* __restrict__ TP, const float* __restrict__ TMi,
               const float* __restrict__ PS, const float* __restrict__ MS,
               float* __restrict__ out)
{
    __shared__ int CV[64 * CV_PITCH];             // 33.0 KB
    __shared__ unsigned char X[70 * X_PITCH];     // 5.6 KB

    const int tid  = threadIdx.x;
    const int lane = tid & 31;
    const int wid  = tid >> 5;       // 0..7 -> m16 tile id (8 * 16 = M 128)
    const int gr   = lane >> 2;      // 0..7
    const int tg   = lane & 3;       // 0..3

    const int co   = tid & 127;
    const int half = tid >> 7;
    const float rtp = TP[co], rtm = TMi[co], rps = PS[co], rms = MS[co];

    // ---- stationary A fragments (weight signs): 56 regs/thread ----
    // A row-major 16x32 frag: row = wid*16 + gr + (j&1)*8,
    //                         kappa = 32*s + (j>>1)*16 + tg*4 + i
    // kappa = j_k*64 + ci  ->  W[row*448 + ci*7 + j_k]
    uint32_t A[KSTEPS][4];
    #pragma unroll
    for (int s = 0; s < KSTEPS; s++) {
        #pragma unroll
        for (int j = 0; j < 4; j++) {
            const int row = wid * 16 + gr + (j & 1) * 8;
            const int kap = 32 * s + (j >> 1) * 16 + tg * 4;
            uint32_t r = 0;
            #pragma unroll
            for (int i = 0; i < 4; i++) {
                const int kk = kap + i;
                const float w = W[row * 448 + (kk & 63) * 7 + (kk >> 6)];
                r |= ((w < 0.f) ? 0xFFu : 0x01u) << (8 * i);
            }
            A[s][j] = r;
        }
    }

    // ---- cross-tile prefetch registers: 5 items x 4 floats ----
    float pf[5][4];

    auto prefetch = [&](unsigned g) {
        if (g >= TOTAL_TILES) return;
        const int b  = (int)(g / TILES_PER_B);
        const int P0 = ((int)g - b * TILES_PER_B) * TILE_OUT * 2;
        const float* Ib = I + (size_t)b * (size_t)CIN * LEN;
        #pragma unroll
        for (int it = 0; it < 5; it++) {
            const int idx = tid + it * NTHREADS;
            if (idx < 16 * 70) {
                const int ci4 = idx / 70;
                const int p   = idx - ci4 * 70;
                const int gl  = P0 - 3 + p;
                const bool inb = (gl >= 0) && (gl < LEN);
                const float* ip = Ib + (size_t)(ci4 * 4) * LEN + gl;
                pf[it][0] = inb ? ip[0]       : -1.f;
                pf[it][1] = inb ? ip[LEN]     : -1.f;
                pf[it][2] = inb ? ip[2 * LEN] : -1.f;
                pf[it][3] = inb ? ip[3 * LEN] : -1.f;
            }
        }
    };

    unsigned g = (unsigned)blockIdx.x;
    prefetch(g);

    while (g < TOTAL_TILES) {
        const unsigned gn = g + GRID;
        const int b  = (int)(g / TILES_PER_B);
        const int jt = (int)g - b * TILES_PER_B;
        const int t0 = jt * TILE_OUT;
        const int nt = min(TILE_OUT, LOUT - t0);

        // ---- convert prefetched floats -> sign tile X[p][ci] ----
        #pragma unroll
        for (int it = 0; it < 5; it++) {
            const int idx = tid + it * NTHREADS;
            if (idx < 16 * 70) {
                const int ci4 = idx / 70;
                const int p   = idx - ci4 * 70;
                const uint32_t pk = ((pf[it][0] < 0.f) ? 0xFFu : 1u)
                                  | (((pf[it][1] < 0.f) ? 0xFFu : 1u) << 8)
                                  | (((pf[it][2] < 0.f) ? 0xFFu : 1u) << 16)
                                  | (((pf[it][3] < 0.f) ? 0xFFu : 1u) << 24);
                *(uint32_t*)&X[p * X_PITCH + ci4 * 4] = pk;
            }
        }
        __syncthreads();            // X ready; prev tile's CV pool reads done

        // ---- kick off next tile's global loads (hidden under MMA) ----
        prefetch(gn);

        // ---- MMA mainloop: 112 IMMA + 224 LDS.32 per warp ----
        int acc[8][4];
        #pragma unroll
        for (int n8 = 0; n8 < 8; n8++)
            #pragma unroll
            for (int r = 0; r < 4; r++) acc[n8][r] = 0;

        #pragma unroll
        for (int s = 0; s < KSTEPS; s++) {
            #pragma unroll
            for (int n8 = 0; n8 < 8; n8++) {
                const int prel = n8 * 8 + gr + (s >> 1);
                const uint32_t* bp =
                    (const uint32_t*)&X[prel * X_PITCH + (s & 1) * 32 + tg * 4];
                const uint32_t b0 = bp[0];
                const uint32_t b1 = bp[4];
                MMA_S8(acc[n8], A[s], b0, b1);
            }
        }

        // ---- stage conv results to CV[n][co] ----
        #pragma unroll
        for (int n8 = 0; n8 < 8; n8++) {
            const int n0 = n8 * 8 + tg * 2;
            const int r0 = wid * 16 + gr;
            CV[n0 * CV_PITCH + r0]           = acc[n8][0];
            CV[(n0 + 1) * CV_PITCH + r0]     = acc[n8][1];
            CV[n0 * CV_PITCH + r0 + 8]       = acc[n8][2];
            CV[(n0 + 1) * CV_PITCH + r0 + 8] = acc[n8][3];
        }
        __syncthreads();            // CV ready; all MMA reads of X done

        // ---- pool(7,2) + threshold + store ----
        {
            const int jo0 = half * 15;
            if (jo0 < nt) {
                float* ob = out + ((size_t)b * COUT + co) * LOUT + t0;
                int qa = max(CV[(2 * jo0) * CV_PITCH + co],
                             CV[(2 * jo0 + 1) * CV_PITCH + co]);
                int qb = max(CV[(2 * jo0 + 2) * CV_PITCH + co],
                             CV[(2 * jo0 + 3) * CV_PITCH + co]);
                #pragma unroll
                for (int k = 0; k < 15; k++) {
                    const int jo = jo0 + k;
                    if (jo < nt && jo < 29) {
                        const int l0 = CV[(2 * jo + 4) * CV_PITCH + co];
                        const int l1 = CV[(2 * jo + 5) * CV_PITCH + co];
                        const int l2 = CV[(2 * jo + 6) * CV_PITCH + co];
                        const int qc = max(l0, l1);
                        const int mi = max(max(qa, qb), max(qc, l2));
                        const float mx = (float)mi;
                        const float pos = (mx > rtp) ? rps : -rps;
                        const float neg = (mx > rtm) ? rms : -rms;
                        ob[jo] = (mx >= 0.f) ? pos : neg;
                        qa = qb; qb = qc;
                    }
                }
            }
        }

        g = gn;
    }
}

extern "C" void kernel_launch(void* const* d_in, const int* in_sizes, int n_in,
                              void* d_out, int out_size) {
    const float* I  = (const float*)d_in[0];
    const float* W  = (const float*)d_in[1];
    const float* tp = (const float*)d_in[2];
    const float* tm = (const float*)d_in[3];
    const float* ps = (const float*)d_in[4];
    const float* ms = (const float*)d_in[5];
    float* out = (float*)d_out;

    binconv_kernel<<<GRID, NTHREADS>>>(I, W, tp, tm, ps, ms, out);
}